// round 8
// baseline (speedup 1.0000x reference)
#include <cuda_runtime.h>
#include <cstdint>

// ---------------------------------------------------------------------------
// Quantized LeNet, B=1024. conv1 dp4a, conv2 + FC1 int8 mma.sync (legacy IMMA
// is the tensor path available at plain sm_103 PTX target; tcgen05 is 'a'-only
// and the harness compiles compute_103). Pool-max commutes with monotone
// quantization -> integer max first; quant chains precomputed into LUTs.
// ---------------------------------------------------------------------------

#define DEVBUF __device__ __align__(16)

__device__ unsigned g_absmax[4];                 // zero-init; atomicMax idempotent
DEVBUF int8_t g_w1q [32 * 9];                    // [oc][tap]
DEVBUF int8_t g_w2m [64 * 384];                  // conv2 B, mma-swizzled
DEVBUF int8_t g_wl1q[4096 * 1600];               // row-major [n][k]
DEVBUF int8_t g_wl2q[10 * 4096];                 // row-major [n][k]
DEVBUF int8_t g_a1  [1024 * 13 * 13 * 32];       // conv1 out NHWC codes
DEVBUF int8_t g_a2  [1024 * 1600];               // conv2 out NCHW-flat codes
DEVBUF int8_t g_a3  [1024 * 4096];               // fc1 out codes [0,15]
DEVBUF int8_t g_lut1[1009];                      // conv1 acc -> code (+504)
DEVBUF int8_t g_lut2[32257];                     // conv2 acc -> code (+16128)
DEVBUF int8_t g_lut3[179201];                    // fc1  acc -> code (+89600)

// ---------------------------------------------------------------------------
__global__ void __launch_bounds__(256) k_absmax_all(
        const float* __restrict__ w1, const float* __restrict__ w2,
        const float* __restrict__ wl1, const float* __restrict__ wl2) {
    int b = blockIdx.x, tid = threadIdx.x;
    float m = 0.f;
    int slot;
    if (b < 2048) {                               // wl1: 1638400 float4
        slot = 2;
        const float4* p = (const float4*)wl1;
        for (int i = b * 256 + tid; i < 1638400; i += 2048 * 256) {
            float4 v = p[i];
            m = fmaxf(fmaxf(fabsf(v.x), fabsf(v.y)),
                      fmaxf(fabsf(v.z), fabsf(v.w)));
        }
    } else if (b < 2088) {                        // wl2
        slot = 3;
        float4 v = ((const float4*)wl2)[(b - 2048) * 256 + tid];
        m = fmaxf(fmaxf(fabsf(v.x), fabsf(v.y)), fmaxf(fabsf(v.z), fabsf(v.w)));
    } else if (b < 2106) {                        // w2
        slot = 1;
        float4 v = ((const float4*)w2)[(b - 2088) * 256 + tid];
        m = fmaxf(fmaxf(fabsf(v.x), fabsf(v.y)), fmaxf(fabsf(v.z), fabsf(v.w)));
    } else {                                      // w1
        slot = 0;
        if (tid < 72) {
            float4 v = ((const float4*)w1)[tid];
            m = fmaxf(fmaxf(fabsf(v.x), fabsf(v.y)),
                      fmaxf(fabsf(v.z), fabsf(v.w)));
        }
    }
#pragma unroll
    for (int o = 16; o > 0; o >>= 1)
        m = fmaxf(m, __shfl_xor_sync(0xffffffffu, m, o));
    if ((tid & 31) == 0)
        atomicMax(&g_absmax[slot], __float_as_uint(m));
}

__device__ __forceinline__ int8_t qw7(float x, float s) {
    float t = rintf(__fdiv_rn(x, s));
    return (int8_t)fminf(fmaxf(t, -7.f), 7.f);
}

// Weight quant + w2 mma-relayout + LUT build, one kernel.
__global__ void __launch_bounds__(256) k_quant_all(
        const float* __restrict__ w1, const float* __restrict__ w2,
        const float* __restrict__ wl1, const float* __restrict__ wl2,
        const float* __restrict__ ps_in, const float* __restrict__ ps_a1,
        const float* __restrict__ ps_a2, const float* __restrict__ ps_a3) {
    int b = blockIdx.x, tid = threadIdx.x;
    if (b < 6400) {                               // wl1 char4
        float s = __fdiv_rn(__uint_as_float(g_absmax[2]), 7.0f);
        int i = b * 256 + tid;
        float4 v = ((const float4*)wl1)[i];
        char4 o;
        o.x = qw7(v.x, s); o.y = qw7(v.y, s);
        o.z = qw7(v.z, s); o.w = qw7(v.w, s);
        ((char4*)g_wl1q)[i] = o;
    } else if (b < 6440) {                        // wl2 char4
        float s = __fdiv_rn(__uint_as_float(g_absmax[3]), 7.0f);
        int i = (b - 6400) * 256 + tid;
        float4 v = ((const float4*)wl2)[i];
        char4 o;
        o.x = qw7(v.x, s); o.y = qw7(v.y, s);
        o.z = qw7(v.z, s); o.w = qw7(v.w, s);
        ((char4*)g_wl2q)[i] = o;
    } else if (b < 6512) {                        // w2 -> swizzled mma layout
        float s = __fdiv_rn(__uint_as_float(g_absmax[1]), 7.0f);
        int i = (b - 6440) * 256 + tid;           // < 18432
        int o = i / 288, rem = i % 288, ci = rem / 9, tap = rem % 9;
        int k = tap * 32 + ci;
        int p = k >> 4;
        g_w2m[o * 384 + (((p ^ (o & 7)) << 4) | (k & 15))] = qw7(w2[i], s);
    } else if (b == 6512) {                       // w1
        float s = __fdiv_rn(__uint_as_float(g_absmax[0]), 7.0f);
        for (int i = tid; i < 288; i += 256) g_w1q[i] = qw7(w1[i], s);
    } else {                                      // LUT build
        int i = (b - 6513) * 256 + tid;
        float s_in = ps_in[0];
        float sw1 = __fdiv_rn(__uint_as_float(g_absmax[0]), 7.0f);
        float sw2 = __fdiv_rn(__uint_as_float(g_absmax[1]), 7.0f);
        float sw3 = __fdiv_rn(__uint_as_float(g_absmax[2]), 7.0f);
        if (i < 1009) {
            float s_a1 = ps_a1[0];
            float v = (float)(i - 504) * (s_in * sw1);
            float t = rintf(__fdiv_rn(v, s_a1));
            t = fminf(fmaxf(t, 0.f), 15.f);
            float t2 = rintf(__fdiv_rn(t * s_a1, s_in));
            g_lut1[i] = (int8_t)fminf(fmaxf(t2, -8.f), 7.f);
        }
        if (i < 32257) {
            float s_a2 = ps_a2[0];
            float v = (float)(i - 16128) * (s_in * sw2);
            float t = rintf(__fdiv_rn(v, s_a2));
            t = fminf(fmaxf(t, 0.f), 15.f);
            float t2 = rintf(__fdiv_rn(t * s_a2, s_in));
            g_lut2[i] = (int8_t)fminf(fmaxf(t2, -8.f), 7.f);
        }
        if (i < 179201) {
            float s_a3 = ps_a3[0];
            float v = (float)(i - 89600) * (s_in * sw3);
            float t = rintf(__fdiv_rn(v, s_a3));
            g_lut3[i] = (int8_t)fminf(fmaxf(t, 0.f), 15.f);
        }
    }
}

// ---------------------------------------------------------------------------
// conv1: quantize x -> 3x3 conv via dp4a -> integer pool-max -> LUT.
__global__ void __launch_bounds__(256) k_conv1(const float* __restrict__ x,
                                               const float* __restrict__ ps_in) {
    __shared__ __align__(4) int8_t sx[28 * 32];
    __shared__ int swa[32][3], swb[32][3];
    __shared__ int8_t slut[1009];
    int b = blockIdx.x, tid = threadIdx.x;
    float s_in = ps_in[0];
    const float* xb = x + b * 784;
    for (int i = tid; i < 784; i += 256) {
        float t = rintf(__fdiv_rn(xb[i], s_in));
        t = fminf(fmaxf(t, -8.f), 7.f);
        sx[(i / 28) * 32 + (i % 28)] = (int8_t)t;
    }
    if (tid < 96) {
        int c = tid / 3, ky = tid % 3;
        int w0 = (int)g_w1q[c * 9 + ky * 3] & 0xff;
        int w1 = (int)g_w1q[c * 9 + ky * 3 + 1] & 0xff;
        int w2 = (int)g_w1q[c * 9 + ky * 3 + 2] & 0xff;
        swa[c][ky] = w0 | (w1 << 8) | (w2 << 16);
        swb[c][ky] = (w0 << 8) | (w1 << 16) | (w2 << 24);
    }
    for (int i = tid; i < 1009; i += 256) slut[i] = g_lut1[i];
    __syncthreads();

    int ch = tid & 31, wq = tid >> 5;
    int wA0 = swa[ch][0], wA1 = swa[ch][1], wA2 = swa[ch][2];
    int wB0 = swb[ch][0], wB1 = swb[ch][1], wB2 = swb[ch][2];
    const int* sxw = (const int*)sx;

    for (int it = 0; it < 22; it++) {
        int win = wq + it * 8;
        if (win >= 169) break;
        int ph = win / 13, pw = win % 13;
        int bytec = 2 * pw, widx = bytec >> 2, sh = bytec & 3;
        int r0 = 2 * ph;
        int rows[4];
#pragma unroll
        for (int r = 0; r < 4; r++) {
            int u = sxw[(r0 + r) * 8 + widx];
            int v = sxw[(r0 + r) * 8 + widx + 1];
            rows[r] = sh ? __byte_perm(u, v, 0x5432) : u;
        }
        int a00 = __dp4a(rows[0], wA0, __dp4a(rows[1], wA1, __dp4a(rows[2], wA2, 0)));
        int a01 = __dp4a(rows[0], wB0, __dp4a(rows[1], wB1, __dp4a(rows[2], wB2, 0)));
        int a10 = __dp4a(rows[1], wA0, __dp4a(rows[2], wA1, __dp4a(rows[3], wA2, 0)));
        int a11 = __dp4a(rows[1], wB0, __dp4a(rows[2], wB1, __dp4a(rows[3], wB2, 0)));
        int amax = max(max(a00, a01), max(a10, a11));
        g_a1[(b * 169 + win) * 32 + ch] = slut[amax + 504];
    }
}

// ---------------------------------------------------------------------------
__device__ __forceinline__ void ldm_x4(uint32_t addr, uint32_t* r) {
    asm volatile("ldmatrix.sync.aligned.m8n8.x4.shared.b16 {%0,%1,%2,%3}, [%4];"
                 : "=r"(r[0]), "=r"(r[1]), "=r"(r[2]), "=r"(r[3]) : "r"(addr));
}
__device__ __forceinline__ void mma_s8(int* c, const uint32_t* a,
                                       uint32_t b0, uint32_t b1) {
    asm volatile(
        "mma.sync.aligned.m16n8k32.row.col.s32.s8.s8.s32 "
        "{%0,%1,%2,%3}, {%4,%5,%6,%7}, {%8,%9}, {%0,%1,%2,%3};"
        : "+r"(c[0]), "+r"(c[1]), "+r"(c[2]), "+r"(c[3])
        : "r"(a[0]), "r"(a[1]), "r"(a[2]), "r"(a[3]), "r"(b0), "r"(b1));
}
#define CPASYNC16(dst, src) \
    asm volatile("cp.async.cg.shared.global [%0], [%1], 16;" \
                 :: "r"(dst), "l"(src) : "memory")
#define CP_COMMIT() asm volatile("cp.async.commit_group;" ::: "memory")

// ---------------------------------------------------------------------------
// conv2 via mma: per image im2col A[112 x 288], B = g_w2m pre-swizzled.
// Pool via shfl-max, then LUT.
__global__ void __launch_bounds__(256, 3) k_conv2() {
    extern __shared__ __align__(16) int8_t dyn2[];
    int8_t* Asm = dyn2;                // 112*384 = 43008
    int8_t* Bsm = dyn2 + 43008;        // 64*384  = 24576
    int b = blockIdx.x, tid = threadIdx.x;
    {
        const int4* src = (const int4*)g_w2m;
        int4* dst = (int4*)Bsm;
#pragma unroll
        for (int i = 0; i < 6; i++) dst[tid + 256 * i] = src[tid + 256 * i];
    }
    {
        const int8_t* img = g_a1 + b * 5408;
        for (int idx = tid; idx < 1800; idx += 256) {
            int r = idx / 18, p = idx - r * 18;
            int win = r >> 2, dp = r & 3;
            int ph = win / 5, pw = win - ph * 5;
            int tap = p >> 1, ky = tap / 3, kx = tap - ky * 3;
            int oy = 2 * ph + (dp >> 1) + ky, ox = 2 * pw + (dp & 1) + kx;
            int4 v = *(const int4*)(img + (oy * 13 + ox) * 32 + (p & 1) * 16);
            *(int4*)(Asm + r * 384 + (((p ^ (r & 7)) << 4))) = v;
        }
    }
    __syncthreads();

    int lane = tid & 31, wid = tid >> 5;
    if (wid >= 7) return;
    int mt = wid;
    int rl = lane & 15, phh = lane >> 4;
    uint32_t smA = (uint32_t)__cvta_generic_to_shared(Asm);
    uint32_t smB = (uint32_t)__cvta_generic_to_shared(Bsm);
    int ra = mt * 16 + rl;
    uint32_t aBase = smA + ra * 384, aXor = (uint32_t)((ra & 7) << 4);
    uint32_t bBase[4], bXor[4];
#pragma unroll
    for (int bt = 0; bt < 4; bt++) {
        int rb = bt * 16 + rl;
        bBase[bt] = smB + rb * 384;
        bXor[bt] = (uint32_t)((rb & 7) << 4);
    }

    int acc[8][4];
#pragma unroll
    for (int i = 0; i < 8; i++)
#pragma unroll
        for (int j = 0; j < 4; j++) acc[i][j] = 0;

#pragma unroll
    for (int s = 0; s < 9; s++) {
        uint32_t pb = (uint32_t)((2 * s + phh) << 4);
        uint32_t af[4];
        ldm_x4(aBase + (pb ^ aXor), af);
        uint32_t bf[4][4];
#pragma unroll
        for (int bt = 0; bt < 4; bt++) ldm_x4(bBase[bt] + (pb ^ bXor[bt]), bf[bt]);
#pragma unroll
        for (int nt = 0; nt < 8; nt++)
            mma_s8(acc[nt], af, bf[nt >> 1][nt & 1], bf[nt >> 1][(nt & 1) + 2]);
    }

    int t4 = lane & 3;
    int winA = mt * 4 + (lane >> 4);
    int winB = winA + 2;
    bool st = ((lane >> 2) & 3) == 0;
    int8_t* dst = g_a2 + b * 1600;
#pragma unroll
    for (int nt = 0; nt < 8; nt++) {
        int m0 = acc[nt][0], m1 = acc[nt][1], m2 = acc[nt][2], m3 = acc[nt][3];
        m0 = max(m0, __shfl_xor_sync(0xffffffffu, m0, 4));
        m0 = max(m0, __shfl_xor_sync(0xffffffffu, m0, 8));
        m1 = max(m1, __shfl_xor_sync(0xffffffffu, m1, 4));
        m1 = max(m1, __shfl_xor_sync(0xffffffffu, m1, 8));
        m2 = max(m2, __shfl_xor_sync(0xffffffffu, m2, 4));
        m2 = max(m2, __shfl_xor_sync(0xffffffffu, m2, 8));
        m3 = max(m3, __shfl_xor_sync(0xffffffffu, m3, 4));
        m3 = max(m3, __shfl_xor_sync(0xffffffffu, m3, 8));
        if (st) {
            int col = nt * 8 + t4 * 2;
            if (winA < 25) {
                dst[col * 25 + winA]       = g_lut2[m0 + 16128];
                dst[(col + 1) * 25 + winA] = g_lut2[m1 + 16128];
            }
            if (winB < 25) {
                dst[col * 25 + winB]       = g_lut2[m2 + 16128];
                dst[(col + 1) * 25 + winB] = g_lut2[m3 + 16128];
            }
        }
    }
}

// ---------------------------------------------------------------------------
// FC1 via int8 mma m16n8k32, BM=128 BN=128 BK=64, 3-stage cp.async pipeline
// (one barrier per chunk; stage (ch+2)%3 written after barrier ch — its last
// reader was chunk ch-1, sealed by that barrier). LUT epilogue.
__global__ void __launch_bounds__(256, 2) k_fc1() {
    __shared__ __align__(16) int8_t As[3][8192];   // 24KB
    __shared__ __align__(16) int8_t Bs[3][8192];   // 24KB
    int tid = threadIdx.x, lane = tid & 31, wid = tid >> 5;
    int wm = wid >> 2, wn = wid & 3;
    int m0 = blockIdx.y * 128, n0 = blockIdx.x * 128;

    int srow = tid >> 2, sp = tid & 3;
    int spp = sp ^ ((srow >> 1) & 3);
    const int8_t* agp = g_a2 + (m0 + srow) * 1600 + sp * 16;
    const int8_t* bgp = g_wl1q + (n0 + srow) * 1600 + sp * 16;
    uint32_t soff = (uint32_t)((srow * 4 + spp) * 16);

    uint32_t sbA = (uint32_t)__cvta_generic_to_shared(As);
    uint32_t sbB = (uint32_t)__cvta_generic_to_shared(Bs);

    int acc[4][4][4];
#pragma unroll
    for (int i = 0; i < 4; i++)
#pragma unroll
        for (int j = 0; j < 4; j++)
#pragma unroll
            for (int k = 0; k < 4; k++) acc[i][j][k] = 0;

    int rl = lane & 15, ph = lane >> 4;
    uint32_t a_addr[4], b_addr[2];
#pragma unroll
    for (int mt = 0; mt < 4; mt++) {
        int r = wm * 64 + mt * 16 + rl;
        int pp = ph ^ ((r >> 1) & 3);
        a_addr[mt] = sbA + (r * 4 + pp) * 16;
    }
#pragma unroll
    for (int bt = 0; bt < 2; bt++) {
        int n = wn * 32 + bt * 16 + rl;
        int pp = ph ^ ((n >> 1) & 3);
        b_addr[bt] = sbB + (n * 4 + pp) * 16;
    }

    // issue chunk ch into stage st (4 x 16B cp.async per thread)
    auto issue = [&](int ch, int st) {
        uint32_t o = (uint32_t)(st * 8192) + soff;
        const int8_t* ag = agp + ch * 64;
        const int8_t* bg = bgp + ch * 64;
        CPASYNC16(sbA + o,        ag);
        CPASYNC16(sbA + o + 4096, ag + 64 * 1600);
        CPASYNC16(sbB + o,        bg);
        CPASYNC16(sbB + o + 4096, bg + 64 * 1600);
        CP_COMMIT();
    };
    issue(0, 0);
    issue(1, 1);

    for (int chk = 0; chk < 25; chk++) {
        if (chk < 24) {
            asm volatile("cp.async.wait_group 1;" ::: "memory");
        } else {
            asm volatile("cp.async.wait_group 0;" ::: "memory");
        }
        __syncthreads();
        if (chk + 2 < 25) issue(chk + 2, (chk + 2) % 3);
        uint32_t stoff = (uint32_t)((chk % 3) * 8192);
#pragma unroll
        for (int ks = 0; ks < 2; ks++) {
            uint32_t kx = ks ? 32u : 0u;           // plane ^2 == byte ^32
            uint32_t af[4][4], bf[2][4];
#pragma unroll
            for (int mt = 0; mt < 4; mt++) ldm_x4((a_addr[mt] ^ kx) + stoff, af[mt]);
#pragma unroll
            for (int bt = 0; bt < 2; bt++) ldm_x4((b_addr[bt] ^ kx) + stoff, bf[bt]);
#pragma unroll
            for (int mt = 0; mt < 4; mt++)
#pragma unroll
                for (int nt = 0; nt < 4; nt++)
                    mma_s8(acc[mt][nt], af[mt],
                           bf[nt >> 1][nt & 1], bf[nt >> 1][(nt & 1) + 2]);
        }
    }

    int g = lane >> 2, t4 = lane & 3;
#pragma unroll
    for (int mt = 0; mt < 4; mt++) {
#pragma unroll
        for (int nt = 0; nt < 4; nt++) {
            int mrow = m0 + wm * 64 + mt * 16 + g;
            int ncol = n0 + wn * 32 + nt * 8 + t4 * 2;
#pragma unroll
            for (int h = 0; h < 2; h++) {
                char2 o;
                o.x = g_lut3[acc[mt][nt][2 * h] + 89600];
                o.y = g_lut3[acc[mt][nt][2 * h + 1] + 89600];
                *(char2*)(g_a3 + (mrow + 8 * h) * 4096 + ncol) = o;
            }
        }
    }
}

// ---------------------------------------------------------------------------
// FC2: [1024,4096] x [10,4096]^T -> f32 out. Two images per block.
__global__ void __launch_bounds__(256) k_fc2(float* __restrict__ out,
                                             const float* __restrict__ ps_a3) {
    __shared__ int red[8][10];
    int tid = threadIdx.x;
    int half = tid >> 7, t = tid & 127;
    int b = blockIdx.x * 2 + half;
    const int* aw = (const int*)g_a3 + b * 1024;
    const int* wp = (const int*)g_wl2q;
    int acc[10];
#pragma unroll
    for (int n = 0; n < 10; n++) acc[n] = 0;
    for (int k = t; k < 1024; k += 128) {
        int a = aw[k];
#pragma unroll
        for (int n = 0; n < 10; n++) acc[n] = __dp4a(a, wp[n * 1024 + k], acc[n]);
    }
#pragma unroll
    for (int n = 0; n < 10; n++)
#pragma unroll
        for (int o = 16; o > 0; o >>= 1)
            acc[n] += __shfl_xor_sync(0xffffffffu, acc[n], o);
    if ((tid & 31) == 0) {
        int w = tid >> 5;
#pragma unroll
        for (int n = 0; n < 10; n++) red[w][n] = acc[n];
    }
    __syncthreads();
    if (t < 10) {
        int w0 = half * 4;
        int s = red[w0][t] + red[w0 + 1][t] + red[w0 + 2][t] + red[w0 + 3][t];
        float s_a3 = ps_a3[0];
        float s_w = __fdiv_rn(__uint_as_float(g_absmax[3]), 7.0f);
        out[b * 10 + t] = (float)s * (s_a3 * s_w);
    }
}

// ---------------------------------------------------------------------------
extern "C" void kernel_launch(void* const* d_in, const int* in_sizes, int n_in,
                              void* d_out, int out_size) {
    const float* x    = (const float*)d_in[0];
    const float* w1   = (const float*)d_in[1];
    const float* w2   = (const float*)d_in[2];
    const float* wl1  = (const float*)d_in[3];
    const float* wl2  = (const float*)d_in[4];
    const float* s_in = (const float*)d_in[5];
    const float* s_a1 = (const float*)d_in[6];
    const float* s_a2 = (const float*)d_in[7];
    const float* s_a3 = (const float*)d_in[8];
    float* out = (float*)d_out;
    (void)in_sizes; (void)n_in; (void)out_size;

    cudaFuncSetAttribute(k_conv2, cudaFuncAttributeMaxDynamicSharedMemorySize,
                         43008 + 24576);

    k_absmax_all<<<2107, 256>>>(w1, w2, wl1, wl2);
    k_quant_all<<<7214, 256>>>(w1, w2, wl1, wl2, s_in, s_a1, s_a2, s_a3);
    k_conv1<<<1024, 256>>>(x, s_in);
    k_conv2<<<1024, 256, 43008 + 24576>>>();
    k_fc1<<<dim3(4096 / 128, 1024 / 128), 256>>>();
    k_fc2<<<512, 256>>>(out, s_a3);
}